// round 3
// baseline (speedup 1.0000x reference)
#include <cuda_runtime.h>

// out[r] = W[0] + b + sum_i W[1+i]*x_i + sum_{i<=j} Wq[i,j]*x_i*x_j
// Split each row across TWO warps: parity-0 warps handle even i-rows of the
// triangle, parity-1 warps odd i-rows. Parity is uniform per warp (tid>>8),
// so the unrolled bodies have compile-time shared-mem offsets and no
// divergence; weight LDS is pure broadcast within a warp.
//
// Inner j-loop uses 2 accumulators to break the serial FFMA chain.

#define DIMS  64
#define NPOLY 2145
#define TPB   512
#define ROWS_PER_BLK 256
#define NBLK  128            // 128 * 256 = 32768 rows exactly

template<int P>
__device__ __forceinline__ float half_sum(const float* __restrict__ ws,
                                          const float xr[DIMS])
{
    float acc = 0.0f;
    #pragma unroll
    for (int m = 0; m < DIMS / 2; m++) {
        const int i = 2 * m + P;                         // compile-time
        const int base = 1 + DIMS + DIMS * i - (i * (i - 1)) / 2;
        float s0 = ws[1 + i];                            // fold linear term
        float s1 = 0.0f;
        int j = i;
        #pragma unroll
        for (; j + 1 < DIMS; j += 2) {
            s0 = fmaf(ws[base + (j - i)],     xr[j],     s0);
            s1 = fmaf(ws[base + (j - i) + 1], xr[j + 1], s1);
        }
        if (j < DIMS)
            s0 = fmaf(ws[base + (j - i)], xr[j], s0);
        acc = fmaf(xr[i], s0 + s1, acc);
    }
    return acc;
}

__global__ void __launch_bounds__(TPB, 1)
poly_model_kernel(const float* __restrict__ x,
                  const float* __restrict__ W,
                  const float* __restrict__ bias,
                  float* __restrict__ out)
{
    __shared__ float ws[NPOLY];
    __shared__ float red[ROWS_PER_BLK];

    const int tid = threadIdx.x;

    #pragma unroll
    for (int k = tid; k < NPOLY; k += TPB) ws[k] = W[k];
    __syncthreads();

    const int p   = tid >> 8;          // 0: warps 0-7, 1: warps 8-15
    const int rl  = tid & 255;
    const int row = blockIdx.x * ROWS_PER_BLK + rl;

    // Row into registers (16 x float4).
    float xr[DIMS];
    const float4* xp = reinterpret_cast<const float4*>(x + (size_t)row * DIMS);
    #pragma unroll
    for (int q = 0; q < DIMS / 4; q++) {
        float4 v = xp[q];
        xr[4*q + 0] = v.x;
        xr[4*q + 1] = v.y;
        xr[4*q + 2] = v.z;
        xr[4*q + 3] = v.w;
    }

    float acc;
    if (p == 0) acc = half_sum<0>(ws, xr);   // uniform branch per warp
    else        acc = half_sum<1>(ws, xr);

    if (p == 1) red[rl] = acc;
    __syncthreads();

    if (p == 0)
        out[row] = acc + red[rl] + ws[0] + bias[0];
}

extern "C" void kernel_launch(void* const* d_in, const int* in_sizes, int n_in,
                              void* d_out, int out_size)
{
    const float* x    = (const float*)d_in[0];  // [32768, 64]
    const float* W    = (const float*)d_in[1];  // [2145]
    const float* bias = (const float*)d_in[2];  // [1]
    float* out = (float*)d_out;                 // [32768]

    poly_model_kernel<<<NBLK, TPB>>>(x, W, bias, out);
}

// round 4
// speedup vs baseline: 1.0443x; 1.0443x over previous
#include <cuda_runtime.h>

// out[r] = W[0] + b + sum_i x_i * ( W[1+i] + sum_{j>=i} Wq[i,j] * x_j )
//
// Shared layout (dynamic):
//   xs  [256][68]  x tile, coalesced-loaded, row stride 272B (conflict-free LDS.128)
//   w2  [64][68]   zero-padded triangular weight rows, each row 16B-aligned
//   wlin[64]       linear weights (folded into s0 init)
//
// One thread per row; inner loop = aligned LDS.128 (broadcast) + 4 FFMA,
// 2 accumulators -> 0.5 FFMA/cyc/warp dependent-chain rate (= SMSP pipe share).

#define DIMS  64
#define DPAD  68
#define TPB   256
#define NBLK  128
#define ROWS  256           // rows per block

#define SMEM_BYTES ((ROWS*DPAD + DIMS*DPAD + DIMS) * 4)

__global__ void __launch_bounds__(TPB, 1)
poly_model_kernel(const float* __restrict__ x,
                  const float* __restrict__ W,
                  const float* __restrict__ bias,
                  float* __restrict__ out)
{
    extern __shared__ float smem[];
    float* xs   = smem;                    // ROWS*DPAD
    float* w2   = smem + ROWS * DPAD;      // DIMS*DPAD
    float* wlin = w2 + DIMS * DPAD;        // DIMS

    const int tid = threadIdx.x;

    // Build padded triangular weight matrix (zeros beyond row length).
    for (int idx = tid; idx < DIMS * DPAD; idx += TPB) {
        const int i = idx / DPAD;
        const int t = idx - i * DPAD;
        const int j = i + t;
        float v = 0.0f;
        if (j < DIMS) {
            const int base = 1 + DIMS + i * DIMS - (i * (i - 1)) / 2;
            v = W[base + t];
        }
        w2[idx] = v;
    }
    if (tid < DIMS) wlin[tid] = W[1 + tid];

    // Coalesced x tile load into padded shared rows.
    const float4* xg = reinterpret_cast<const float4*>(x)
                     + (size_t)blockIdx.x * ROWS * (DIMS / 4);
    #pragma unroll
    for (int k = 0; k < ROWS * (DIMS / 4) / TPB; k++) {   // 16 iters
        const int q  = tid + k * TPB;
        const int r  = q >> 4;            // float4s per row = 16
        const int c4 = q & 15;
        *reinterpret_cast<float4*>(&xs[r * DPAD + c4 * 4]) = xg[q];
    }
    // Zero the 4 pad columns of each row (one row per thread).
    {
        const float4 z = make_float4(0.f, 0.f, 0.f, 0.f);
        *reinterpret_cast<float4*>(&xs[tid * DPAD + DIMS]) = z;
    }
    __syncthreads();

    // Row into registers (17 x LDS.128, conflict-free via 272B stride).
    float xr[DPAD];
    #pragma unroll
    for (int k = 0; k < DPAD / 4; k++) {
        float4 v = *reinterpret_cast<const float4*>(&xs[tid * DPAD + 4 * k]);
        xr[4*k + 0] = v.x;
        xr[4*k + 1] = v.y;
        xr[4*k + 2] = v.z;
        xr[4*k + 3] = v.w;
    }

    float acc = 0.0f;
    #pragma unroll
    for (int i = 0; i < DIMS; i++) {
        const int Lp = (DIMS - i + 3) & ~3;        // padded row length
        float s0 = wlin[i];                         // linear term folded in
        float s1 = 0.0f;
        #pragma unroll
        for (int t4 = 0; t4 < Lp / 4; t4++) {
            const float4 w = *reinterpret_cast<const float4*>(&w2[i * DPAD + 4 * t4]);
            s0 = fmaf(w.x, xr[i + 4*t4 + 0], s0);
            s1 = fmaf(w.y, xr[i + 4*t4 + 1], s1);
            s0 = fmaf(w.z, xr[i + 4*t4 + 2], s0);
            s1 = fmaf(w.w, xr[i + 4*t4 + 3], s1);
        }
        acc = fmaf(xr[i], s0 + s1, acc);
    }

    out[blockIdx.x * ROWS + tid] = acc + W[0] + bias[0];
}

extern "C" void kernel_launch(void* const* d_in, const int* in_sizes, int n_in,
                              void* d_out, int out_size)
{
    const float* x    = (const float*)d_in[0];  // [32768, 64]
    const float* W    = (const float*)d_in[1];  // [2145]
    const float* bias = (const float*)d_in[2];  // [1]
    float* out = (float*)d_out;                 // [32768]

    cudaFuncSetAttribute(poly_model_kernel,
                         cudaFuncAttributeMaxDynamicSharedMemorySize, SMEM_BYTES);
    poly_model_kernel<<<NBLK, TPB, SMEM_BYTES>>>(x, W, bias, out);
}